// round 1
// baseline (speedup 1.0000x reference)
#include <cuda_runtime.h>
#include <math.h>

// Problem constants
#define B_ 2
#define S_ 2048
#define D_ 1024
#define H_ 16
#define HD_ 64

// Scratch: q, k, v (head-interleaved [B,S,D] layout) + attention concat output
__device__ float g_q[B_ * S_ * D_];
__device__ float g_k[B_ * S_ * D_];
__device__ float g_v[B_ * S_ * D_];
__device__ float g_cat[B_ * S_ * D_];

// ---------------------------------------------------------------------------
// Generic batched tiled GEMM.
//   TB = true :  C[m,n] = alpha * sum_k A[m,k] * B[n,k]   (A @ B^T)
//   TB = false:  C[m,n] = alpha * sum_k A[m,k] * B[k,n]   (A @ B)
// Per-z (blockIdx.z) base offsets: z -> (b = z/Hdiv, h = z%Hdiv),
//   ptr += b*off?b + h*off?h.
// Tiling: 64x64 block tile, BK=16, 256 threads, 4x4 micro-tile per thread.
// All of M, N divisible by 64 and K divisible by 16 (true for every call).
// ---------------------------------------------------------------------------
template <bool TB>
__global__ __launch_bounds__(256) void gemm_kernel(
    const float* __restrict__ A, const float* __restrict__ Bm,
    float* __restrict__ C,
    int M, int N, int K, int lda, int ldb, int ldc,
    long offAb, long offAh, long offBb, long offBh, long offCb, long offCh,
    int Hdiv, float alpha)
{
    const int z = blockIdx.z;
    const int b = z / Hdiv;
    const int h = z % Hdiv;
    A  += (long)b * offAb + (long)h * offAh;
    Bm += (long)b * offBb + (long)h * offBh;
    C  += (long)b * offCb + (long)h * offCh;

    __shared__ float As[16][64];
    __shared__ float Bs[16][64];

    const int tid = threadIdx.x;
    const int tx = tid & 15;        // 0..15  -> N direction (4 cols each)
    const int ty = tid >> 4;        // 0..15  -> M direction (4 rows each)

    const int m0 = blockIdx.y * 64;
    const int n0 = blockIdx.x * 64;

    float acc[4][4];
#pragma unroll
    for (int i = 0; i < 4; i++)
#pragma unroll
        for (int j = 0; j < 4; j++) acc[i][j] = 0.0f;

    for (int kt = 0; kt < K; kt += 16) {
        // --- load A tile [64 rows x 16 k] into As[k][m] ---
        {
            const int r  = tid >> 2;   // 0..63 row within tile
            const int c4 = tid & 3;    // 0..3  float4 within 16-wide k
            float4 av = *reinterpret_cast<const float4*>(
                &A[(long)(m0 + r) * lda + kt + c4 * 4]);
            As[c4 * 4 + 0][r] = av.x;
            As[c4 * 4 + 1][r] = av.y;
            As[c4 * 4 + 2][r] = av.z;
            As[c4 * 4 + 3][r] = av.w;
        }
        // --- load B tile into Bs[k][n] ---
        if (TB) {
            // B is [N,K] row-major; tile rows are n, cols are k
            const int r  = tid >> 2;   // 0..63 n within tile
            const int c4 = tid & 3;
            float4 bv = *reinterpret_cast<const float4*>(
                &Bm[(long)(n0 + r) * ldb + kt + c4 * 4]);
            Bs[c4 * 4 + 0][r] = bv.x;
            Bs[c4 * 4 + 1][r] = bv.y;
            Bs[c4 * 4 + 2][r] = bv.z;
            Bs[c4 * 4 + 3][r] = bv.w;
        } else {
            // B is [K,N] row-major; tile rows are k, cols are n
            const int r = tid >> 4;    // 0..15 k within tile
            const int c = tid & 15;    // 0..15 float4 within 64-wide n
            float4 bv = *reinterpret_cast<const float4*>(
                &Bm[(long)(kt + r) * ldb + n0 + c * 4]);
            *reinterpret_cast<float4*>(&Bs[r][c * 4]) = bv;
        }
        __syncthreads();

#pragma unroll
        for (int k = 0; k < 16; k++) {
            float4 a = reinterpret_cast<const float4*>(&As[k][0])[ty];
            float4 bb = reinterpret_cast<const float4*>(&Bs[k][0])[tx];
            float ra[4] = {a.x, a.y, a.z, a.w};
            float rb[4] = {bb.x, bb.y, bb.z, bb.w};
#pragma unroll
            for (int i = 0; i < 4; i++)
#pragma unroll
                for (int j = 0; j < 4; j++)
                    acc[i][j] = fmaf(ra[i], rb[j], acc[i][j]);
        }
        __syncthreads();
    }

    // --- store C ---
#pragma unroll
    for (int i = 0; i < 4; i++) {
        float4 cv;
        cv.x = acc[i][0] * alpha;
        cv.y = acc[i][1] * alpha;
        cv.z = acc[i][2] * alpha;
        cv.w = acc[i][3] * alpha;
        *reinterpret_cast<float4*>(
            &C[(long)(m0 + ty * 4 + i) * ldc + n0 + tx * 4]) = cv;
    }
}

// ---------------------------------------------------------------------------
// Row-wise softmax, in place. One block (256 threads) per row of `ncols`.
// ---------------------------------------------------------------------------
__global__ __launch_bounds__(256) void softmax_rows(float* __restrict__ W, int ncols)
{
    const long row = blockIdx.x;
    float* p = W + row * (long)ncols;
    const int t = threadIdx.x;

    __shared__ float red[256];

    float m = -INFINITY;
    for (int i = t; i < ncols; i += 256) m = fmaxf(m, p[i]);
    red[t] = m;
    __syncthreads();
    for (int s = 128; s > 0; s >>= 1) {
        if (t < s) red[t] = fmaxf(red[t], red[t + s]);
        __syncthreads();
    }
    m = red[0];
    __syncthreads();

    float sum = 0.0f;
    for (int i = t; i < ncols; i += 256) {
        float e = __expf(p[i] - m);
        p[i] = e;
        sum += e;
    }
    red[t] = sum;
    __syncthreads();
    for (int s = 128; s > 0; s >>= 1) {
        if (t < s) red[t] += red[t + s];
        __syncthreads();
    }
    float inv = 1.0f / red[0];
    for (int i = t; i < ncols; i += 256) p[i] *= inv;
}

// ---------------------------------------------------------------------------
extern "C" void kernel_launch(void* const* d_in, const int* in_sizes, int n_in,
                              void* d_out, int out_size)
{
    const float* Q  = (const float*)d_in[0];
    const float* K  = (const float*)d_in[1];
    const float* V  = (const float*)d_in[2];
    const float* Wq = (const float*)d_in[3];
    const float* Wk = (const float*)d_in[4];
    const float* Wv = (const float*)d_in[5];
    const float* Wo = (const float*)d_in[6];

    float* out = (float*)d_out;
    float* final_out = out;                                  // [B,S,D]
    float* weights   = out + (long)B_ * S_ * D_;             // [B,H,S,S]

    float *q, *k, *v, *cat;
    cudaGetSymbolAddress((void**)&q,   g_q);
    cudaGetSymbolAddress((void**)&k,   g_k);
    cudaGetSymbolAddress((void**)&v,   g_v);
    cudaGetSymbolAddress((void**)&cat, g_cat);

    const int BS = B_ * S_;   // 4096
    const float scale = 0.125f;  // 1/sqrt(HD)

    // 1) Projections: q/k/v = X @ W^T   [4096,1024] x [1024,1024]^T
    {
        dim3 grid(D_ / 64, BS / 64, 1);
        gemm_kernel<true><<<grid, 256>>>(Q, Wq, q, BS, D_, D_, D_, D_, D_,
                                         0, 0, 0, 0, 0, 0, 1, 1.0f);
        gemm_kernel<true><<<grid, 256>>>(K, Wk, k, BS, D_, D_, D_, D_, D_,
                                         0, 0, 0, 0, 0, 0, 1, 1.0f);
        gemm_kernel<true><<<grid, 256>>>(V, Wv, v, BS, D_, D_, D_, D_, D_,
                                         0, 0, 0, 0, 0, 0, 1, 1.0f);
    }

    // 2) scores = scale * q_h @ k_h^T  -> weights buffer (pre-softmax)
    {
        dim3 grid(S_ / 64, S_ / 64, B_ * H_);
        gemm_kernel<true><<<grid, 256>>>(
            q, k, weights, S_, S_, HD_,
            D_, D_, S_,
            (long)S_ * D_, (long)HD_,          // A offsets (b,h)
            (long)S_ * D_, (long)HD_,          // B offsets (b,h)
            (long)H_ * S_ * S_, (long)S_ * S_, // C offsets (b,h)
            H_, scale);
    }

    // 3) softmax in place over last dim
    softmax_rows<<<B_ * H_ * S_, 256>>>(weights, S_);

    // 4) out_h = weights_h @ v_h  -> concat layout [B,S,D]
    {
        dim3 grid(HD_ / 64, S_ / 64, B_ * H_);
        gemm_kernel<false><<<grid, 256>>>(
            weights, v, cat, S_, HD_, S_,
            S_, D_, D_,
            (long)H_ * S_ * S_, (long)S_ * S_,
            (long)S_ * D_, (long)HD_,
            (long)S_ * D_, (long)HD_,
            H_, 1.0f);
    }

    // 5) final = cat @ Wo^T
    {
        dim3 grid(D_ / 64, BS / 64, 1);
        gemm_kernel<true><<<grid, 256>>>(cat, Wo, final_out, BS, D_, D_,
                                         D_, D_, D_,
                                         0, 0, 0, 0, 0, 0, 1, 1.0f);
    }
}

// round 2
// speedup vs baseline: 1.2072x; 1.2072x over previous
#include <cuda_runtime.h>
#include <math.h>

// Problem constants
#define B_ 2
#define S_ 2048
#define D_ 1024
#define H_ 16
#define HD_ 64

// Scratch buffers
__device__ float g_q[B_ * S_ * D_];
__device__ float g_k[B_ * S_ * D_];
__device__ float g_v[B_ * S_ * D_];
__device__ float g_cat[B_ * S_ * D_];

// ---------------------------------------------------------------------------
// Batched tiled GEMM, register-blocked + double-buffered smem.
//   TB = true :  C[m,n] = alpha * sum_k A[m,k] * B[n,k]   (A @ B^T)
//   TB = false:  C[m,n] = alpha * sum_k A[m,k] * B[k,n]   (A @ B)
// 256 threads. Block tile BM x BN, K-panel BK. Micro-tile 8 x (BN/16),
// split into 4-wide chunks at {t*4, t*4 + dim/2} for conflict-free LDS.128.
// Requires: M % BM == 0, N % BN == 0, K % BK == 0 (true for all calls here).
// ---------------------------------------------------------------------------
template <bool TB, int BM, int BN, int BK>
__global__ __launch_bounds__(256) void gemm_kernel(
    const float* __restrict__ A, const float* __restrict__ Bm,
    float* __restrict__ C,
    int M, int N, int K, int lda, int ldb, int ldc,
    long offAb, long offAh, long offBb, long offBh, long offCb, long offCh,
    int Hdiv, float alpha)
{
    constexpr int TM = 8;
    constexpr int TN = BN / 16;            // 8 for BN=128, 4 for BN=64
    constexpr int A_F4 = BM * BK / 1024;   // float4 loads per thread for A
    constexpr int B_F4 = BN * BK / 1024;   // float4 loads per thread for B

    const int z = blockIdx.z;
    const int b = z / Hdiv;
    const int h = z % Hdiv;
    A  += (long)b * offAb + (long)h * offAh;
    Bm += (long)b * offBb + (long)h * offBh;
    C  += (long)b * offCb + (long)h * offCh;

    __shared__ float As[2][BK][BM];
    __shared__ float Bs[2][BK][BN];

    const int tid = threadIdx.x;
    const int tx = tid & 15;   // N direction
    const int ty = tid >> 4;   // M direction

    const int m0 = blockIdx.y * BM;
    const int n0 = blockIdx.x * BN;

    float acc[TM][TN];
#pragma unroll
    for (int i = 0; i < TM; i++)
#pragma unroll
        for (int j = 0; j < TN; j++) acc[i][j] = 0.0f;

    float4 ra[A_F4], rb[B_F4];

    // ---- global load helpers ----
    auto gloadA = [&](int kt) {
#pragma unroll
        for (int i = 0; i < A_F4; i++) {
            int f4  = tid + i * 256;
            int row = f4 / (BK / 4);
            int c4  = f4 % (BK / 4);
            ra[i] = *reinterpret_cast<const float4*>(
                &A[(long)(m0 + row) * lda + kt + c4 * 4]);
        }
    };
    auto gloadB = [&](int kt) {
        if (TB) {
#pragma unroll
            for (int i = 0; i < B_F4; i++) {
                int f4  = tid + i * 256;
                int row = f4 / (BK / 4);
                int c4  = f4 % (BK / 4);
                rb[i] = *reinterpret_cast<const float4*>(
                    &Bm[(long)(n0 + row) * ldb + kt + c4 * 4]);
            }
        } else {
#pragma unroll
            for (int i = 0; i < B_F4; i++) {
                int f4 = tid + i * 256;
                int kr = f4 / (BN / 4);
                int c  = f4 % (BN / 4);
                rb[i] = *reinterpret_cast<const float4*>(
                    &Bm[(long)(kt + kr) * ldb + n0 + c * 4]);
            }
        }
    };
    auto sstore = [&](int buf) {
#pragma unroll
        for (int i = 0; i < A_F4; i++) {
            int f4  = tid + i * 256;
            int row = f4 / (BK / 4);
            int c4  = f4 % (BK / 4);
            As[buf][c4 * 4 + 0][row] = ra[i].x;
            As[buf][c4 * 4 + 1][row] = ra[i].y;
            As[buf][c4 * 4 + 2][row] = ra[i].z;
            As[buf][c4 * 4 + 3][row] = ra[i].w;
        }
        if (TB) {
#pragma unroll
            for (int i = 0; i < B_F4; i++) {
                int f4  = tid + i * 256;
                int row = f4 / (BK / 4);
                int c4  = f4 % (BK / 4);
                Bs[buf][c4 * 4 + 0][row] = rb[i].x;
                Bs[buf][c4 * 4 + 1][row] = rb[i].y;
                Bs[buf][c4 * 4 + 2][row] = rb[i].z;
                Bs[buf][c4 * 4 + 3][row] = rb[i].w;
            }
        } else {
#pragma unroll
            for (int i = 0; i < B_F4; i++) {
                int f4 = tid + i * 256;
                int kr = f4 / (BN / 4);
                int c  = f4 % (BN / 4);
                *reinterpret_cast<float4*>(&Bs[buf][kr][c * 4]) = rb[i];
            }
        }
    };
    auto compute = [&](int buf) {
#pragma unroll
        for (int k = 0; k < BK; k++) {
            float a[TM], bfr[TN];
            *reinterpret_cast<float4*>(&a[0]) =
                *reinterpret_cast<const float4*>(&As[buf][k][ty * 4]);
            *reinterpret_cast<float4*>(&a[4]) =
                *reinterpret_cast<const float4*>(&As[buf][k][ty * 4 + BM / 2]);
            *reinterpret_cast<float4*>(&bfr[0]) =
                *reinterpret_cast<const float4*>(&Bs[buf][k][tx * 4]);
            if (TN == 8)
                *reinterpret_cast<float4*>(&bfr[4]) =
                    *reinterpret_cast<const float4*>(&Bs[buf][k][tx * 4 + BN / 2]);
#pragma unroll
            for (int i = 0; i < TM; i++)
#pragma unroll
                for (int j = 0; j < TN; j++)
                    acc[i][j] = fmaf(a[i], bfr[j], acc[i][j]);
        }
    };

    // ---- main loop: double buffered ----
    gloadA(0); gloadB(0);
    sstore(0);
    __syncthreads();
    int buf = 0;
    for (int kt = BK; kt < K; kt += BK) {
        gloadA(kt); gloadB(kt);
        compute(buf);
        sstore(buf ^ 1);
        __syncthreads();
        buf ^= 1;
    }
    compute(buf);

    // ---- epilogue ----
#pragma unroll
    for (int im = 0; im < TM; im++) {
        int m = m0 + ((im < 4) ? (ty * 4 + im) : (BM / 2 + ty * 4 + im - 4));
        float4 c0;
        c0.x = acc[im][0] * alpha;
        c0.y = acc[im][1] * alpha;
        c0.z = acc[im][2] * alpha;
        c0.w = acc[im][3] * alpha;
        *reinterpret_cast<float4*>(&C[(long)m * ldc + n0 + tx * 4]) = c0;
        if (TN == 8) {
            float4 c1;
            c1.x = acc[im][4] * alpha;
            c1.y = acc[im][5] * alpha;
            c1.z = acc[im][6] * alpha;
            c1.w = acc[im][7] * alpha;
            *reinterpret_cast<float4*>(
                &C[(long)m * ldc + n0 + BN / 2 + tx * 4]) = c1;
        }
    }
}

// ---------------------------------------------------------------------------
// Row-wise softmax, in place. One block (256 threads) per row.
// ---------------------------------------------------------------------------
__global__ __launch_bounds__(256) void softmax_rows(float* __restrict__ W, int ncols)
{
    const long row = blockIdx.x;
    float* p = W + row * (long)ncols;
    const int t = threadIdx.x;

    __shared__ float red[256];

    float m = -INFINITY;
    for (int i = t; i < ncols; i += 256) m = fmaxf(m, p[i]);
    red[t] = m;
    __syncthreads();
    for (int s = 128; s > 0; s >>= 1) {
        if (t < s) red[t] = fmaxf(red[t], red[t + s]);
        __syncthreads();
    }
    m = red[0];
    __syncthreads();

    float sum = 0.0f;
    for (int i = t; i < ncols; i += 256) {
        float e = __expf(p[i] - m);
        p[i] = e;
        sum += e;
    }
    red[t] = sum;
    __syncthreads();
    for (int s = 128; s > 0; s >>= 1) {
        if (t < s) red[t] += red[t + s];
        __syncthreads();
    }
    float inv = 1.0f / red[0];
    for (int i = t; i < ncols; i += 256) p[i] *= inv;
}

// ---------------------------------------------------------------------------
extern "C" void kernel_launch(void* const* d_in, const int* in_sizes, int n_in,
                              void* d_out, int out_size)
{
    const float* Q  = (const float*)d_in[0];
    const float* K  = (const float*)d_in[1];
    const float* V  = (const float*)d_in[2];
    const float* Wq = (const float*)d_in[3];
    const float* Wk = (const float*)d_in[4];
    const float* Wv = (const float*)d_in[5];
    const float* Wo = (const float*)d_in[6];

    float* out = (float*)d_out;
    float* final_out = out;                       // [B,S,D]
    float* weights   = out + (long)B_ * S_ * D_;  // [B,H,S,S]

    float *q, *k, *v, *cat;
    cudaGetSymbolAddress((void**)&q,   g_q);
    cudaGetSymbolAddress((void**)&k,   g_k);
    cudaGetSymbolAddress((void**)&v,   g_v);
    cudaGetSymbolAddress((void**)&cat, g_cat);

    const int BS = B_ * S_;      // 4096
    const float scale = 0.125f;  // 1/sqrt(HD)

    // 1) Projections: q/k/v = X @ W^T   [4096,1024] x [1024,1024]^T
    {
        dim3 grid(D_ / 128, BS / 128, 1);
        gemm_kernel<true, 128, 128, 16><<<grid, 256>>>(
            Q, Wq, q, BS, D_, D_, D_, D_, D_, 0, 0, 0, 0, 0, 0, 1, 1.0f);
        gemm_kernel<true, 128, 128, 16><<<grid, 256>>>(
            K, Wk, k, BS, D_, D_, D_, D_, D_, 0, 0, 0, 0, 0, 0, 1, 1.0f);
        gemm_kernel<true, 128, 128, 16><<<grid, 256>>>(
            V, Wv, v, BS, D_, D_, D_, D_, D_, 0, 0, 0, 0, 0, 0, 1, 1.0f);
    }

    // 2) scores = scale * q_h @ k_h^T  -> weights buffer (pre-softmax)
    {
        dim3 grid(S_ / 128, S_ / 128, B_ * H_);
        gemm_kernel<true, 128, 128, 16><<<grid, 256>>>(
            q, k, weights, S_, S_, HD_,
            D_, D_, S_,
            (long)S_ * D_, (long)HD_,
            (long)S_ * D_, (long)HD_,
            (long)H_ * S_ * S_, (long)S_ * S_,
            H_, scale);
    }

    // 3) softmax in place over last dim
    softmax_rows<<<B_ * H_ * S_, 256>>>(weights, S_);

    // 4) out_h = weights_h @ v_h  -> concat layout [B,S,D]
    {
        dim3 grid(HD_ / 64, S_ / 128, B_ * H_);
        gemm_kernel<false, 128, 64, 16><<<grid, 256>>>(
            weights, v, cat, S_, HD_, S_,
            S_, D_, D_,
            (long)H_ * S_ * S_, (long)S_ * S_,
            (long)S_ * D_, (long)HD_,
            (long)S_ * D_, (long)HD_,
            H_, 1.0f);
    }

    // 5) final = cat @ Wo^T
    {
        dim3 grid(D_ / 128, BS / 128, 1);
        gemm_kernel<true, 128, 128, 16><<<grid, 256>>>(
            cat, Wo, final_out, BS, D_, D_, D_, D_, D_,
            0, 0, 0, 0, 0, 0, 1, 1.0f);
    }
}

// round 4
// speedup vs baseline: 2.2073x; 1.8284x over previous
#include <cuda_runtime.h>
#include <cuda_bf16.h>
#include <stdint.h>
#include <math.h>

#define B_ 2
#define S_ 2048
#define D_ 1024
#define H_ 16
#define HD_ 64
#define BS_ (B_*S_)

// ---------------- bf16 split scratch ----------------
__device__ __nv_bfloat16 g_iQh[BS_*D_], g_iQl[BS_*D_];
__device__ __nv_bfloat16 g_iKh[BS_*D_], g_iKl[BS_*D_];
__device__ __nv_bfloat16 g_iVh[BS_*D_], g_iVl[BS_*D_];
__device__ __nv_bfloat16 g_wqh[D_*D_], g_wql[D_*D_];
__device__ __nv_bfloat16 g_wkh[D_*D_], g_wkl[D_*D_];
__device__ __nv_bfloat16 g_wvh[D_*D_], g_wvl[D_*D_];
__device__ __nv_bfloat16 g_woh[D_*D_], g_wol[D_*D_];
__device__ __nv_bfloat16 g_qh[BS_*D_], g_ql[BS_*D_];
__device__ __nv_bfloat16 g_kh[BS_*D_], g_kl[BS_*D_];
__device__ __nv_bfloat16 g_vth[BS_*D_], g_vtl[BS_*D_];   // [B,H,HD,S]
__device__ __nv_bfloat16 g_cath[BS_*D_], g_catl[BS_*D_]; // [B,S,D]

// ---------------- helpers ----------------
__device__ __forceinline__ uint32_t smem_u32(const void* p){
    uint32_t a;
    asm("{ .reg .u64 t; cvta.to.shared.u64 t, %1; cvt.u32.u64 %0, t; }" : "=r"(a) : "l"(p));
    return a;
}
__device__ __forceinline__ void ldmat_x4(uint32_t& r0, uint32_t& r1, uint32_t& r2,
                                         uint32_t& r3, uint32_t addr){
    asm volatile("ldmatrix.sync.aligned.m8n8.x4.shared.b16 {%0,%1,%2,%3}, [%4];"
        : "=r"(r0), "=r"(r1), "=r"(r2), "=r"(r3) : "r"(addr));
}
__device__ __forceinline__ void mma_bf16(float& d0, float& d1, float& d2, float& d3,
                                         uint32_t a0, uint32_t a1, uint32_t a2, uint32_t a3,
                                         uint32_t b0, uint32_t b1){
    asm volatile("mma.sync.aligned.m16n8k16.row.col.f32.bf16.bf16.f32 "
        "{%0,%1,%2,%3}, {%4,%5,%6,%7}, {%8,%9}, {%0,%1,%2,%3};"
        : "+f"(d0), "+f"(d1), "+f"(d2), "+f"(d3)
        : "r"(a0), "r"(a1), "r"(a2), "r"(a3), "r"(b0), "r"(b1));
}
__device__ __forceinline__ uint32_t pack_bf16x2(float a, float b){
    __nv_bfloat162 v = __floats2bfloat162_rn(a, b);
    return *reinterpret_cast<uint32_t*>(&v);
}
__device__ __forceinline__ void split2(float a, float b, uint32_t& h, uint32_t& l){
    __nv_bfloat16 ha = __float2bfloat16(a), hb = __float2bfloat16(b);
    h = ((uint32_t)__bfloat16_as_ushort(ha)) | (((uint32_t)__bfloat16_as_ushort(hb)) << 16);
    l = pack_bf16x2(a - __bfloat162float(ha), b - __bfloat162float(hb));
}
__device__ __forceinline__ void split8(const float4& x0, const float4& x1,
                                       uint4& h, uint4& l){
    split2(x0.x, x0.y, h.x, l.x);
    split2(x0.z, x0.w, h.y, l.y);
    split2(x1.x, x1.y, h.z, l.z);
    split2(x1.z, x1.w, h.w, l.w);
}

// ---------------- fp32 -> (hi, lo) bf16 split, elementwise ----------------
__global__ __launch_bounds__(256) void split_kernel(
    const float* __restrict__ in, __nv_bfloat16* __restrict__ hi,
    __nv_bfloat16* __restrict__ lo, int n)
{
    int i = (blockIdx.x * 256 + threadIdx.x) * 4;
    if (i >= n) return;
    float4 x = *reinterpret_cast<const float4*>(in + i);
    uint32_t h0, l0, h1, l1;
    split2(x.x, x.y, h0, l0);
    split2(x.z, x.w, h1, l1);
    *reinterpret_cast<uint2*>(hi + i) = make_uint2(h0, h1);
    *reinterpret_cast<uint2*>(lo + i) = make_uint2(l0, l1);
}

// ---------------------------------------------------------------------------
// Split-bf16 GEMM on mma.sync.m16n8k16.  C[m,n] = alpha * sum_k A[m,k]*B[n,k].
//   BM=128, BK=32, BN in {128,64}. 256 threads (8 warps). Double-buffered
//   dynamic smem with register prefetch. 80-byte padded rows (40 bf16) for
//   conflict-free ldmatrix.
//   AMODE 0: A pre-split bf16.  AMODE 1: A fp32, split on load.
//   EPI 0: fp32 store (*alpha).  EPI 1: split-bf16 store.
//   EPI 2: split-bf16 per-head transposed store into [B,H,HD,S].
// ---------------------------------------------------------------------------
template <int BN, int AMODE, int EPI>
__global__ __launch_bounds__(256, 1) void mma_gemm(
    const void* __restrict__ Ah_, const void* __restrict__ Al_,
    const __nv_bfloat16* __restrict__ Bh, const __nv_bfloat16* __restrict__ Bl,
    float* __restrict__ C, __nv_bfloat16* __restrict__ Chi, __nv_bfloat16* __restrict__ Clo,
    int K, int lda, int ldb, int ldc,
    long offAb, long offAh, long offBb, long offBh, long offCb, long offCh,
    int Hdiv, float alpha)
{
    constexpr int BM = 128;
    constexpr int BK = 32;
    constexpr int ROWB = 80;                  // padded row bytes (40 bf16)
    constexpr int ATILE = BM * ROWB;          // 10240 B
    constexpr int BTILE = BN * ROWB;
    constexpr int STAGE = 2 * ATILE + 2 * BTILE;
    constexpr int AF4 = BM * BK / 8 / 256;    // uint4 per thread per A tile (=2)
    constexpr int BF4 = BN * BK / 8 / 256;    // 2 (BN=128) or 1 (BN=64)
    constexpr int WARPS_M = (BN == 128) ? 2 : 4;
    constexpr int WARPS_N = 8 / WARPS_M;
    constexpr int MT = BM / (WARPS_M * 16);   // 4 or 2
    constexpr int NT = BN / (WARPS_N * 8);    // 4

    extern __shared__ char smem[];
    const uint32_t sbase = smem_u32(smem);

    const int tid  = threadIdx.x;
    const int lane = tid & 31;
    const int wid  = tid >> 5;

    const int z = blockIdx.z;
    const int bb = z / Hdiv, hh = z % Hdiv;
    const long aoff = (long)bb * offAb + (long)hh * offAh;
    const long boff = (long)bb * offBb + (long)hh * offBh;
    const long coff = (long)bb * offCb + (long)hh * offCh;

    const int m0 = blockIdx.y * BM;
    const int n0 = blockIdx.x * BN;

    const int m_warp = (wid % WARPS_M) * (BM / WARPS_M);
    const int n_warp = (wid / WARPS_M) * (BN / WARPS_N);

    // smem offsets within a stage
    const uint32_t OFF_AH = 0, OFF_AL = ATILE, OFF_BH = 2 * ATILE, OFF_BL = 2 * ATILE + BTILE;

    float acc[MT][NT][4];
#pragma unroll
    for (int i = 0; i < MT; i++)
#pragma unroll
        for (int j = 0; j < NT; j++)
#pragma unroll
            for (int r = 0; r < 4; r++) acc[i][j][r] = 0.0f;

    uint4 rAh[AF4], rAl[AF4], rBh[BF4], rBl[BF4];

    auto gload = [&](int it) {
        const int kt = it * BK;
        if (AMODE == 0) {
            const __nv_bfloat16* Ah = (const __nv_bfloat16*)Ah_ + aoff;
            const __nv_bfloat16* Al = (const __nv_bfloat16*)Al_ + aoff;
#pragma unroll
            for (int i = 0; i < AF4; i++) {
                int f4 = tid + i * 256;
                int row = f4 >> 2, c8 = f4 & 3;
                long g = (long)(m0 + row) * lda + kt + c8 * 8;
                rAh[i] = *reinterpret_cast<const uint4*>(Ah + g);
                rAl[i] = *reinterpret_cast<const uint4*>(Al + g);
            }
        } else {
            const float* A = (const float*)Ah_ + aoff;
#pragma unroll
            for (int i = 0; i < AF4; i++) {
                int f4 = tid + i * 256;
                int row = f4 >> 2, c8 = f4 & 3;
                long g = (long)(m0 + row) * lda + kt + c8 * 8;
                float4 x0 = *reinterpret_cast<const float4*>(A + g);
                float4 x1 = *reinterpret_cast<const float4*>(A + g + 4);
                split8(x0, x1, rAh[i], rAl[i]);
            }
        }
#pragma unroll
        for (int i = 0; i < BF4; i++) {
            int f4 = tid + i * 256;
            int row = f4 >> 2, c8 = f4 & 3;
            long g = boff + (long)(n0 + row) * ldb + kt + c8 * 8;
            rBh[i] = *reinterpret_cast<const uint4*>(Bh + g);
            rBl[i] = *reinterpret_cast<const uint4*>(Bl + g);
        }
    };

    auto sstore = [&](int buf) {
        char* st = smem + buf * STAGE;
#pragma unroll
        for (int i = 0; i < AF4; i++) {
            int f4 = tid + i * 256;
            int row = f4 >> 2, c8 = f4 & 3;
            uint32_t o = row * ROWB + c8 * 16;
            *reinterpret_cast<uint4*>(st + OFF_AH + o) = rAh[i];
            *reinterpret_cast<uint4*>(st + OFF_AL + o) = rAl[i];
        }
#pragma unroll
        for (int i = 0; i < BF4; i++) {
            int f4 = tid + i * 256;
            int row = f4 >> 2, c8 = f4 & 3;
            uint32_t o = row * ROWB + c8 * 16;
            *reinterpret_cast<uint4*>(st + OFF_BH + o) = rBh[i];
            *reinterpret_cast<uint4*>(st + OFF_BL + o) = rBl[i];
        }
    };

    auto compute = [&](int buf) {
        const uint32_t st = sbase + buf * STAGE;
        // A fragment address: row = m_warp + im*16 + (lane&15), col8 = (lane>>4)
        const uint32_t a_row = m_warp + (lane & 15);
        const uint32_t a_k8  = (lane >> 4) * 16;           // bytes (8 bf16)
        // B fragment address (x4 over 2 n-tiles):
        const uint32_t b_row = n_warp + (lane & 7) + ((lane >> 4) & 1) * 8;
        const uint32_t b_k8  = ((lane >> 3) & 1) * 16;     // bytes
#pragma unroll
        for (int ks = 0; ks < 2; ks++) {
            const uint32_t kbyte = ks * 32;                // 16 bf16
            uint32_t ah[MT][4], al[MT][4];
#pragma unroll
            for (int im = 0; im < MT; im++) {
                uint32_t addr = st + OFF_AH + (a_row + im * 16) * ROWB + kbyte + a_k8;
                ldmat_x4(ah[im][0], ah[im][1], ah[im][2], ah[im][3], addr);
                addr += ATILE;  // OFF_AL - OFF_AH
                ldmat_x4(al[im][0], al[im][1], al[im][2], al[im][3], addr);
            }
            uint32_t bh[NT][2], bl[NT][2];
#pragma unroll
            for (int j2 = 0; j2 < NT / 2; j2++) {
                uint32_t addr = st + OFF_BH + (b_row + j2 * 16) * ROWB + kbyte + b_k8;
                ldmat_x4(bh[j2*2][0], bh[j2*2][1], bh[j2*2+1][0], bh[j2*2+1][1], addr);
                addr += BTILE;  // OFF_BL - OFF_BH
                ldmat_x4(bl[j2*2][0], bl[j2*2][1], bl[j2*2+1][0], bl[j2*2+1][1], addr);
            }
#pragma unroll
            for (int im = 0; im < MT; im++)
#pragma unroll
                for (int jn = 0; jn < NT; jn++) {
                    float* d = acc[im][jn];
                    mma_bf16(d[0], d[1], d[2], d[3],
                             ah[im][0], ah[im][1], ah[im][2], ah[im][3],
                             bh[jn][0], bh[jn][1]);
                    mma_bf16(d[0], d[1], d[2], d[3],
                             ah[im][0], ah[im][1], ah[im][2], ah[im][3],
                             bl[jn][0], bl[jn][1]);
                    mma_bf16(d[0], d[1], d[2], d[3],
                             al[im][0], al[im][1], al[im][2], al[im][3],
                             bh[jn][0], bh[jn][1]);
                }
        }
    };

    // ---- main loop ----
    const int NI = K / BK;
    gload(0);
    sstore(0);
    __syncthreads();
    int buf = 0;
    for (int it = 1; it < NI; it++) {
        gload(it);
        compute(buf);
        sstore(buf ^ 1);
        __syncthreads();
        buf ^= 1;
    }
    compute(buf);

    // ---- epilogue ----
    const int rbase = m0 + m_warp + (lane >> 2);
    const int cbase = n0 + n_warp + (lane & 3) * 2;
#pragma unroll
    for (int im = 0; im < MT; im++) {
#pragma unroll
        for (int jn = 0; jn < NT; jn++) {
            const float* d = acc[im][jn];
            int r0 = rbase + im * 16;
            int c  = cbase + jn * 8;
            if (EPI == 0) {
                float2 v0 = make_float2(d[0] * alpha, d[1] * alpha);
                float2 v1 = make_float2(d[2] * alpha, d[3] * alpha);
                *reinterpret_cast<float2*>(C + coff + (long)r0 * ldc + c) = v0;
                *reinterpret_cast<float2*>(C + coff + (long)(r0 + 8) * ldc + c) = v1;
            } else if (EPI == 1) {
                uint32_t h, l;
                split2(d[0], d[1], h, l);
                long b0a = coff + (long)r0 * ldc + c;
                *reinterpret_cast<uint32_t*>(Chi + b0a) = h;
                *reinterpret_cast<uint32_t*>(Clo + b0a) = l;
                split2(d[2], d[3], h, l);
                long b1a = coff + (long)(r0 + 8) * ldc + c;
                *reinterpret_cast<uint32_t*>(Chi + b1a) = h;
                *reinterpret_cast<uint32_t*>(Clo + b1a) = l;
            } else {
#pragma unroll
                for (int e = 0; e < 4; e++) {
                    int m = r0 + (e >> 1) * 8;
                    int n = c + (e & 1);
                    float f = d[e];
                    __nv_bfloat16 hv = __float2bfloat16(f);
                    __nv_bfloat16 lv = __float2bfloat16(f - __bfloat162float(hv));
                    int b2 = m >> 11, s2 = m & (S_ - 1);
                    int hidx = n >> 6, hd = n & 63;
                    long addr = (((long)b2 * H_ + hidx) * HD_ + hd) * S_ + s2;
                    Chi[addr] = hv;
                    Clo[addr] = lv;
                }
            }
        }
    }
}

// ---------------- softmax ----------------
__global__ __launch_bounds__(256) void softmax_rows(float* __restrict__ W, int ncols)
{
    const long row = blockIdx.x;
    float* p = W + row * (long)ncols;
    const int t = threadIdx.x;
    __shared__ float red[256];

    float m = -INFINITY;
    for (int i = t; i < ncols; i += 256) m = fmaxf(m, p[i]);
    red[t] = m; __syncthreads();
    for (int s = 128; s > 0; s >>= 1) { if (t < s) red[t] = fmaxf(red[t], red[t+s]); __syncthreads(); }
    m = red[0]; __syncthreads();

    float sum = 0.0f;
    for (int i = t; i < ncols; i += 256) { float e = __expf(p[i] - m); p[i] = e; sum += e; }
    red[t] = sum; __syncthreads();
    for (int s = 128; s > 0; s >>= 1) { if (t < s) red[t] += red[t+s]; __syncthreads(); }
    float inv = 1.0f / red[0];
    for (int i = t; i < ncols; i += 256) p[i] *= inv;
}

// ---------------------------------------------------------------------------
extern "C" void kernel_launch(void* const* d_in, const int* in_sizes, int n_in,
                              void* d_out, int out_size)
{
    const float* Q  = (const float*)d_in[0];
    const float* K  = (const float*)d_in[1];
    const float* V  = (const float*)d_in[2];
    const float* Wq = (const float*)d_in[3];
    const float* Wk = (const float*)d_in[4];
    const float* Wv = (const float*)d_in[5];
    const float* Wo = (const float*)d_in[6];

    float* out = (float*)d_out;
    float* final_out = out;                       // [B,S,D]
    float* weights   = out + (long)B_ * S_ * D_;  // [B,H,S,S]

    __nv_bfloat16 *iQh,*iQl,*iKh,*iKl,*iVh,*iVl;
    __nv_bfloat16 *wqh,*wql,*wkh,*wkl,*wvh,*wvl,*woh,*wol;
    __nv_bfloat16 *qh,*ql,*kh,*kl,*vth,*vtl,*cath,*catl;
    cudaGetSymbolAddress((void**)&iQh, g_iQh); cudaGetSymbolAddress((void**)&iQl, g_iQl);
    cudaGetSymbolAddress((void**)&iKh, g_iKh); cudaGetSymbolAddress((void**)&iKl, g_iKl);
    cudaGetSymbolAddress((void**)&iVh, g_iVh); cudaGetSymbolAddress((void**)&iVl, g_iVl);
    cudaGetSymbolAddress((void**)&wqh, g_wqh); cudaGetSymbolAddress((void**)&wql, g_wql);
    cudaGetSymbolAddress((void**)&wkh, g_wkh); cudaGetSymbolAddress((void**)&wkl, g_wkl);
    cudaGetSymbolAddress((void**)&wvh, g_wvh); cudaGetSymbolAddress((void**)&wvl, g_wvl);
    cudaGetSymbolAddress((void**)&woh, g_woh); cudaGetSymbolAddress((void**)&wol, g_wol);
    cudaGetSymbolAddress((void**)&qh,  g_qh);  cudaGetSymbolAddress((void**)&ql,  g_ql);
    cudaGetSymbolAddress((void**)&kh,  g_kh);  cudaGetSymbolAddress((void**)&kl,  g_kl);
    cudaGetSymbolAddress((void**)&vth, g_vth); cudaGetSymbolAddress((void**)&vtl, g_vtl);
    cudaGetSymbolAddress((void**)&cath,g_cath);cudaGetSymbolAddress((void**)&catl,g_catl);

    constexpr int ROWB = 80;
    constexpr int SM128 = 2 * (2 * 128 * ROWB + 2 * 128 * ROWB);  // 81920
    constexpr int SM64  = 2 * (2 * 128 * ROWB + 2 * 64 * ROWB);   // 61440

    cudaFuncSetAttribute(mma_gemm<128,0,1>, cudaFuncAttributeMaxDynamicSharedMemorySize, SM128);
    cudaFuncSetAttribute(mma_gemm<128,0,2>, cudaFuncAttributeMaxDynamicSharedMemorySize, SM128);
    cudaFuncSetAttribute(mma_gemm<128,0,0>, cudaFuncAttributeMaxDynamicSharedMemorySize, SM128);
    cudaFuncSetAttribute(mma_gemm<64,1,1>,  cudaFuncAttributeMaxDynamicSharedMemorySize, SM64);

    // 0) split fp32 inputs into bf16 hi/lo
    split_kernel<<<BS_*D_/1024, 256>>>(Q, iQh, iQl, BS_*D_);
    split_kernel<<<BS_*D_/1024, 256>>>(K, iKh, iKl, BS_*D_);
    split_kernel<<<BS_*D_/1024, 256>>>(V, iVh, iVl, BS_*D_);
    split_kernel<<<D_*D_/1024, 256>>>(Wq, wqh, wql, D_*D_);
    split_kernel<<<D_*D_/1024, 256>>>(Wk, wkh, wkl, D_*D_);
    split_kernel<<<D_*D_/1024, 256>>>(Wv, wvh, wvl, D_*D_);
    split_kernel<<<D_*D_/1024, 256>>>(Wo, woh, wol, D_*D_);

    // 1) projections: q, k (split-bf16 out); v -> per-head transposed split-bf16
    {
        dim3 g(D_/128, BS_/128, 1);
        mma_gemm<128,0,1><<<g, 256, SM128>>>(iQh, iQl, wqh, wql,
            nullptr, qh, ql, D_, D_, D_, D_, 0,0,0,0,0,0, 1, 1.0f);
        mma_gemm<128,0,1><<<g, 256, SM128>>>(iKh, iKl, wkh, wkl,
            nullptr, kh, kl, D_, D_, D_, D_, 0,0,0,0,0,0, 1, 1.0f);
        mma_gemm<128,0,2><<<g, 256, SM128>>>(iVh, iVl, wvh, wvl,
            nullptr, vth, vtl, D_, D_, D_, D_, 0,0,0,0,0,0, 1, 1.0f);
    }

    // 2) scores = 0.125 * q @ k^T -> weights (fp32, pre-softmax)
    {
        dim3 g(S_/128, S_/128, B_*H_);
        mma_gemm<128,0,0><<<g, 256, SM128>>>(qh, ql, kh, kl,
            weights, nullptr, nullptr,
            HD_, D_, D_, S_,
            (long)S_*D_, (long)HD_, (long)S_*D_, (long)HD_,
            (long)H_*S_*S_, (long)S_*S_, H_, 0.125f);
    }

    // 3) softmax in place
    softmax_rows<<<B_*H_*S_, 256>>>(weights, S_);

    // 4) cat = softmax(scores) @ v  (A fp32 split on load; B = v^T per head)
    {
        dim3 g(1, S_/128, B_*H_);
        mma_gemm<64,1,1><<<g, 256, SM64>>>(weights, nullptr, vth, vtl,
            nullptr, cath, catl,
            S_, S_, S_, D_,
            (long)H_*S_*S_, (long)S_*S_,
            (long)H_*HD_*S_, (long)HD_*S_,
            (long)S_*D_, (long)HD_, H_, 1.0f);
    }

    // 5) final = cat @ Wo^T (fp32 out)
    {
        dim3 g(D_/128, BS_/128, 1);
        mma_gemm<128,0,0><<<g, 256, SM128>>>(cath, catl, woh, wol,
            final_out, nullptr, nullptr,
            D_, D_, D_, D_, 0,0,0,0,0,0, 1, 1.0f);
    }
}

// round 5
// speedup vs baseline: 2.3649x; 1.0714x over previous
#include <cuda_runtime.h>
#include <cuda_bf16.h>
#include <stdint.h>
#include <math.h>

#define B_ 2
#define S_ 2048
#define D_ 1024
#define H_ 16
#define HD_ 64
#define BS_ (B_*S_)

// ---------------- bf16 split scratch ----------------
__device__ __nv_bfloat16 g_iQh[BS_*D_], g_iQl[BS_*D_];
__device__ __nv_bfloat16 g_iKh[BS_*D_], g_iKl[BS_*D_];
__device__ __nv_bfloat16 g_iVh[BS_*D_], g_iVl[BS_*D_];
__device__ __nv_bfloat16 g_wqh[D_*D_], g_wql[D_*D_];
__device__ __nv_bfloat16 g_wkh[D_*D_], g_wkl[D_*D_];
__device__ __nv_bfloat16 g_wvh[D_*D_], g_wvl[D_*D_];
__device__ __nv_bfloat16 g_woh[D_*D_], g_wol[D_*D_];
__device__ __nv_bfloat16 g_qh[BS_*D_], g_ql[BS_*D_];
__device__ __nv_bfloat16 g_kh[BS_*D_], g_kl[BS_*D_];
__device__ __nv_bfloat16 g_vth[BS_*D_], g_vtl[BS_*D_];   // [B,H,HD,S]
__device__ __nv_bfloat16 g_cath[BS_*D_], g_catl[BS_*D_]; // [B,S,D]

// ---------------- helpers ----------------
__device__ __forceinline__ uint32_t smem_u32(const void* p){
    uint32_t a;
    asm("{ .reg .u64 t; cvta.to.shared.u64 t, %1; cvt.u32.u64 %0, t; }" : "=r"(a) : "l"(p));
    return a;
}
__device__ __forceinline__ void ldmat_x4(uint32_t& r0, uint32_t& r1, uint32_t& r2,
                                         uint32_t& r3, uint32_t addr){
    asm volatile("ldmatrix.sync.aligned.m8n8.x4.shared.b16 {%0,%1,%2,%3}, [%4];"
        : "=r"(r0), "=r"(r1), "=r"(r2), "=r"(r3) : "r"(addr));
}
__device__ __forceinline__ void mma_bf16(float& d0, float& d1, float& d2, float& d3,
                                         uint32_t a0, uint32_t a1, uint32_t a2, uint32_t a3,
                                         uint32_t b0, uint32_t b1){
    asm volatile("mma.sync.aligned.m16n8k16.row.col.f32.bf16.bf16.f32 "
        "{%0,%1,%2,%3}, {%4,%5,%6,%7}, {%8,%9}, {%0,%1,%2,%3};"
        : "+f"(d0), "+f"(d1), "+f"(d2), "+f"(d3)
        : "r"(a0), "r"(a1), "r"(a2), "r"(a3), "r"(b0), "r"(b1));
}
__device__ __forceinline__ uint32_t pack_bf16x2(float a, float b){
    __nv_bfloat162 v = __floats2bfloat162_rn(a, b);
    return *reinterpret_cast<uint32_t*>(&v);
}
__device__ __forceinline__ void split2(float a, float b, uint32_t& h, uint32_t& l){
    __nv_bfloat16 ha = __float2bfloat16(a), hb = __float2bfloat16(b);
    h = ((uint32_t)__bfloat16_as_ushort(ha)) | (((uint32_t)__bfloat16_as_ushort(hb)) << 16);
    l = pack_bf16x2(a - __bfloat162float(ha), b - __bfloat162float(hb));
}
__device__ __forceinline__ void split8(const float4& x0, const float4& x1,
                                       uint4& h, uint4& l){
    split2(x0.x, x0.y, h.x, l.x);
    split2(x0.z, x0.w, h.y, l.y);
    split2(x1.x, x1.y, h.z, l.z);
    split2(x1.z, x1.w, h.w, l.w);
}

// ---------------- fp32 -> (hi, lo) bf16 split, elementwise ----------------
__global__ __launch_bounds__(256) void split_kernel(
    const float* __restrict__ in, __nv_bfloat16* __restrict__ hi,
    __nv_bfloat16* __restrict__ lo, int n)
{
    int i = (blockIdx.x * 256 + threadIdx.x) * 4;
    if (i >= n) return;
    float4 x = *reinterpret_cast<const float4*>(in + i);
    uint32_t h0, l0, h1, l1;
    split2(x.x, x.y, h0, l0);
    split2(x.z, x.w, h1, l1);
    *reinterpret_cast<uint2*>(hi + i) = make_uint2(h0, h1);
    *reinterpret_cast<uint2*>(lo + i) = make_uint2(l0, l1);
}

// ---------------------------------------------------------------------------
// Split-bf16 GEMM on mma.sync.m16n8k16.  C[m,n] = alpha * sum_k A[m,k]*B[n,k].
// (unchanged from round 4)
// ---------------------------------------------------------------------------
template <int BN, int AMODE, int EPI>
__global__ __launch_bounds__(256, 1) void mma_gemm(
    const void* __restrict__ Ah_, const void* __restrict__ Al_,
    const __nv_bfloat16* __restrict__ Bh, const __nv_bfloat16* __restrict__ Bl,
    float* __restrict__ C, __nv_bfloat16* __restrict__ Chi, __nv_bfloat16* __restrict__ Clo,
    int K, int lda, int ldb, int ldc,
    long offAb, long offAh, long offBb, long offBh, long offCb, long offCh,
    int Hdiv, float alpha)
{
    constexpr int BM = 128;
    constexpr int BK = 32;
    constexpr int ROWB = 80;
    constexpr int ATILE = BM * ROWB;
    constexpr int BTILE = BN * ROWB;
    constexpr int STAGE = 2 * ATILE + 2 * BTILE;
    constexpr int AF4 = BM * BK / 8 / 256;
    constexpr int BF4 = BN * BK / 8 / 256;
    constexpr int WARPS_M = (BN == 128) ? 2 : 4;
    constexpr int WARPS_N = 8 / WARPS_M;
    constexpr int MT = BM / (WARPS_M * 16);
    constexpr int NT = BN / (WARPS_N * 8);

    extern __shared__ char smem[];
    const uint32_t sbase = smem_u32(smem);

    const int tid  = threadIdx.x;
    const int lane = tid & 31;
    const int wid  = tid >> 5;

    const int z = blockIdx.z;
    const int bb = z / Hdiv, hh = z % Hdiv;
    const long aoff = (long)bb * offAb + (long)hh * offAh;
    const long boff = (long)bb * offBb + (long)hh * offBh;
    const long coff = (long)bb * offCb + (long)hh * offCh;

    const int m0 = blockIdx.y * BM;
    const int n0 = blockIdx.x * BN;

    const int m_warp = (wid % WARPS_M) * (BM / WARPS_M);
    const int n_warp = (wid / WARPS_M) * (BN / WARPS_N);

    const uint32_t OFF_AH = 0, OFF_AL = ATILE, OFF_BH = 2 * ATILE, OFF_BL = 2 * ATILE + BTILE;

    float acc[MT][NT][4];
#pragma unroll
    for (int i = 0; i < MT; i++)
#pragma unroll
        for (int j = 0; j < NT; j++)
#pragma unroll
            for (int r = 0; r < 4; r++) acc[i][j][r] = 0.0f;

    uint4 rAh[AF4], rAl[AF4], rBh[BF4], rBl[BF4];

    auto gload = [&](int it) {
        const int kt = it * BK;
        if (AMODE == 0) {
            const __nv_bfloat16* Ah = (const __nv_bfloat16*)Ah_ + aoff;
            const __nv_bfloat16* Al = (const __nv_bfloat16*)Al_ + aoff;
#pragma unroll
            for (int i = 0; i < AF4; i++) {
                int f4 = tid + i * 256;
                int row = f4 >> 2, c8 = f4 & 3;
                long g = (long)(m0 + row) * lda + kt + c8 * 8;
                rAh[i] = *reinterpret_cast<const uint4*>(Ah + g);
                rAl[i] = *reinterpret_cast<const uint4*>(Al + g);
            }
        } else {
            const float* A = (const float*)Ah_ + aoff;
#pragma unroll
            for (int i = 0; i < AF4; i++) {
                int f4 = tid + i * 256;
                int row = f4 >> 2, c8 = f4 & 3;
                long g = (long)(m0 + row) * lda + kt + c8 * 8;
                float4 x0 = *reinterpret_cast<const float4*>(A + g);
                float4 x1 = *reinterpret_cast<const float4*>(A + g + 4);
                split8(x0, x1, rAh[i], rAl[i]);
            }
        }
#pragma unroll
        for (int i = 0; i < BF4; i++) {
            int f4 = tid + i * 256;
            int row = f4 >> 2, c8 = f4 & 3;
            long g = boff + (long)(n0 + row) * ldb + kt + c8 * 8;
            rBh[i] = *reinterpret_cast<const uint4*>(Bh + g);
            rBl[i] = *reinterpret_cast<const uint4*>(Bl + g);
        }
    };

    auto sstore = [&](int buf) {
        char* st = smem + buf * STAGE;
#pragma unroll
        for (int i = 0; i < AF4; i++) {
            int f4 = tid + i * 256;
            int row = f4 >> 2, c8 = f4 & 3;
            uint32_t o = row * ROWB + c8 * 16;
            *reinterpret_cast<uint4*>(st + OFF_AH + o) = rAh[i];
            *reinterpret_cast<uint4*>(st + OFF_AL + o) = rAl[i];
        }
#pragma unroll
        for (int i = 0; i < BF4; i++) {
            int f4 = tid + i * 256;
            int row = f4 >> 2, c8 = f4 & 3;
            uint32_t o = row * ROWB + c8 * 16;
            *reinterpret_cast<uint4*>(st + OFF_BH + o) = rBh[i];
            *reinterpret_cast<uint4*>(st + OFF_BL + o) = rBl[i];
        }
    };

    auto compute = [&](int buf) {
        const uint32_t st = sbase + buf * STAGE;
        const uint32_t a_row = m_warp + (lane & 15);
        const uint32_t a_k8  = (lane >> 4) * 16;
        const uint32_t b_row = n_warp + (lane & 7) + ((lane >> 4) & 1) * 8;
        const uint32_t b_k8  = ((lane >> 3) & 1) * 16;
#pragma unroll
        for (int ks = 0; ks < 2; ks++) {
            const uint32_t kbyte = ks * 32;
            uint32_t ah[MT][4], al[MT][4];
#pragma unroll
            for (int im = 0; im < MT; im++) {
                uint32_t addr = st + OFF_AH + (a_row + im * 16) * ROWB + kbyte + a_k8;
                ldmat_x4(ah[im][0], ah[im][1], ah[im][2], ah[im][3], addr);
                addr += ATILE;
                ldmat_x4(al[im][0], al[im][1], al[im][2], al[im][3], addr);
            }
            uint32_t bh[NT][2], bl[NT][2];
#pragma unroll
            for (int j2 = 0; j2 < NT / 2; j2++) {
                uint32_t addr = st + OFF_BH + (b_row + j2 * 16) * ROWB + kbyte + b_k8;
                ldmat_x4(bh[j2*2][0], bh[j2*2][1], bh[j2*2+1][0], bh[j2*2+1][1], addr);
                addr += BTILE;
                ldmat_x4(bl[j2*2][0], bl[j2*2][1], bl[j2*2+1][0], bl[j2*2+1][1], addr);
            }
#pragma unroll
            for (int im = 0; im < MT; im++)
#pragma unroll
                for (int jn = 0; jn < NT; jn++) {
                    float* d = acc[im][jn];
                    mma_bf16(d[0], d[1], d[2], d[3],
                             ah[im][0], ah[im][1], ah[im][2], ah[im][3],
                             bh[jn][0], bh[jn][1]);
                    mma_bf16(d[0], d[1], d[2], d[3],
                             ah[im][0], ah[im][1], ah[im][2], ah[im][3],
                             bl[jn][0], bl[jn][1]);
                    mma_bf16(d[0], d[1], d[2], d[3],
                             al[im][0], al[im][1], al[im][2], al[im][3],
                             bh[jn][0], bh[jn][1]);
                }
        }
    };

    const int NI = K / BK;
    gload(0);
    sstore(0);
    __syncthreads();
    int buf = 0;
    for (int it = 1; it < NI; it++) {
        gload(it);
        compute(buf);
        sstore(buf ^ 1);
        __syncthreads();
        buf ^= 1;
    }
    compute(buf);

    const int rbase = m0 + m_warp + (lane >> 2);
    const int cbase = n0 + n_warp + (lane & 3) * 2;
#pragma unroll
    for (int im = 0; im < MT; im++) {
#pragma unroll
        for (int jn = 0; jn < NT; jn++) {
            const float* d = acc[im][jn];
            int r0 = rbase + im * 16;
            int c  = cbase + jn * 8;
            if (EPI == 0) {
                float2 v0 = make_float2(d[0] * alpha, d[1] * alpha);
                float2 v1 = make_float2(d[2] * alpha, d[3] * alpha);
                *reinterpret_cast<float2*>(C + coff + (long)r0 * ldc + c) = v0;
                *reinterpret_cast<float2*>(C + coff + (long)(r0 + 8) * ldc + c) = v1;
            } else if (EPI == 1) {
                uint32_t h, l;
                split2(d[0], d[1], h, l);
                long b0a = coff + (long)r0 * ldc + c;
                *reinterpret_cast<uint32_t*>(Chi + b0a) = h;
                *reinterpret_cast<uint32_t*>(Clo + b0a) = l;
                split2(d[2], d[3], h, l);
                long b1a = coff + (long)(r0 + 8) * ldc + c;
                *reinterpret_cast<uint32_t*>(Chi + b1a) = h;
                *reinterpret_cast<uint32_t*>(Clo + b1a) = l;
            } else {
#pragma unroll
                for (int e = 0; e < 4; e++) {
                    int m = r0 + (e >> 1) * 8;
                    int n = c + (e & 1);
                    float f = d[e];
                    __nv_bfloat16 hv = __float2bfloat16(f);
                    __nv_bfloat16 lv = __float2bfloat16(f - __bfloat162float(hv));
                    int b2 = m >> 11, s2 = m & (S_ - 1);
                    int hidx = n >> 6, hd = n & 63;
                    long addr = (((long)b2 * H_ + hidx) * HD_ + hd) * S_ + s2;
                    Chi[addr] = hv;
                    Clo[addr] = lv;
                }
            }
        }
    }
}

// ---------------------------------------------------------------------------
// Register-resident softmax: one block per 2048-wide row, 256 threads x 8
// floats in registers. Exactly ONE gmem read and ONE gmem write per element.
// ---------------------------------------------------------------------------
__global__ __launch_bounds__(256) void softmax_rows2048(float* __restrict__ W)
{
    float4* p = reinterpret_cast<float4*>(W + (long)blockIdx.x * S_);
    const int t = threadIdx.x;
    const int lane = t & 31, warp = t >> 5;

    __shared__ float red[8];

    // load 8 floats (two coalesced float4 chunks)
    float4 x0 = p[t];
    float4 x1 = p[t + 256];

    // --- row max ---
    float m = fmaxf(fmaxf(fmaxf(x0.x, x0.y), fmaxf(x0.z, x0.w)),
                    fmaxf(fmaxf(x1.x, x1.y), fmaxf(x1.z, x1.w)));
#pragma unroll
    for (int s = 16; s > 0; s >>= 1)
        m = fmaxf(m, __shfl_xor_sync(0xFFFFFFFFu, m, s));
    if (lane == 0) red[warp] = m;
    __syncthreads();
    {
        float v = red[lane & 7];
#pragma unroll
        for (int s = 4; s > 0; s >>= 1)
            v = fmaxf(v, __shfl_xor_sync(0xFFFFFFFFu, v, s));
        m = v;
    }

    // --- exp + row sum ---
    x0.x = __expf(x0.x - m); x0.y = __expf(x0.y - m);
    x0.z = __expf(x0.z - m); x0.w = __expf(x0.w - m);
    x1.x = __expf(x1.x - m); x1.y = __expf(x1.y - m);
    x1.z = __expf(x1.z - m); x1.w = __expf(x1.w - m);
    float sum = (x0.x + x0.y) + (x0.z + x0.w) + (x1.x + x1.y) + (x1.z + x1.w);
#pragma unroll
    for (int s = 16; s > 0; s >>= 1)
        sum += __shfl_xor_sync(0xFFFFFFFFu, sum, s);
    __syncthreads();
    if (lane == 0) red[warp] = sum;
    __syncthreads();
    {
        float v = red[lane & 7];
#pragma unroll
        for (int s = 4; s > 0; s >>= 1)
            v += __shfl_xor_sync(0xFFFFFFFFu, v, s);
        sum = v;
    }

    const float inv = 1.0f / sum;
    x0.x *= inv; x0.y *= inv; x0.z *= inv; x0.w *= inv;
    x1.x *= inv; x1.y *= inv; x1.z *= inv; x1.w *= inv;
    p[t] = x0;
    p[t + 256] = x1;
}

// ---------------------------------------------------------------------------
extern "C" void kernel_launch(void* const* d_in, const int* in_sizes, int n_in,
                              void* d_out, int out_size)
{
    const float* Q  = (const float*)d_in[0];
    const float* K  = (const float*)d_in[1];
    const float* V  = (const float*)d_in[2];
    const float* Wq = (const float*)d_in[3];
    const float* Wk = (const float*)d_in[4];
    const float* Wv = (const float*)d_in[5];
    const float* Wo = (const float*)d_in[6];

    float* out = (float*)d_out;
    float* final_out = out;                       // [B,S,D]
    float* weights   = out + (long)B_ * S_ * D_;  // [B,H,S,S]

    __nv_bfloat16 *iQh,*iQl,*iKh,*iKl,*iVh,*iVl;
    __nv_bfloat16 *wqh,*wql,*wkh,*wkl,*wvh,*wvl,*woh,*wol;
    __nv_bfloat16 *qh,*ql,*kh,*kl,*vth,*vtl,*cath,*catl;
    cudaGetSymbolAddress((void**)&iQh, g_iQh); cudaGetSymbolAddress((void**)&iQl, g_iQl);
    cudaGetSymbolAddress((void**)&iKh, g_iKh); cudaGetSymbolAddress((void**)&iKl, g_iKl);
    cudaGetSymbolAddress((void**)&iVh, g_iVh); cudaGetSymbolAddress((void**)&iVl, g_iVl);
    cudaGetSymbolAddress((void**)&wqh, g_wqh); cudaGetSymbolAddress((void**)&wql, g_wql);
    cudaGetSymbolAddress((void**)&wkh, g_wkh); cudaGetSymbolAddress((void**)&wkl, g_wkl);
    cudaGetSymbolAddress((void**)&wvh, g_wvh); cudaGetSymbolAddress((void**)&wvl, g_wvl);
    cudaGetSymbolAddress((void**)&woh, g_woh); cudaGetSymbolAddress((void**)&wol, g_wol);
    cudaGetSymbolAddress((void**)&qh,  g_qh);  cudaGetSymbolAddress((void**)&ql,  g_ql);
    cudaGetSymbolAddress((void**)&kh,  g_kh);  cudaGetSymbolAddress((void**)&kl,  g_kl);
    cudaGetSymbolAddress((void**)&vth, g_vth); cudaGetSymbolAddress((void**)&vtl, g_vtl);
    cudaGetSymbolAddress((void**)&cath,g_cath);cudaGetSymbolAddress((void**)&catl,g_catl);

    constexpr int ROWB = 80;
    constexpr int SM128 = 2 * (2 * 128 * ROWB + 2 * 128 * ROWB);  // 81920
    constexpr int SM64  = 2 * (2 * 128 * ROWB + 2 * 64 * ROWB);   // 61440

    cudaFuncSetAttribute(mma_gemm<128,0,1>, cudaFuncAttributeMaxDynamicSharedMemorySize, SM128);
    cudaFuncSetAttribute(mma_gemm<128,0,2>, cudaFuncAttributeMaxDynamicSharedMemorySize, SM128);
    cudaFuncSetAttribute(mma_gemm<128,0,0>, cudaFuncAttributeMaxDynamicSharedMemorySize, SM128);
    cudaFuncSetAttribute(mma_gemm<64,1,1>,  cudaFuncAttributeMaxDynamicSharedMemorySize, SM64);

    // 0) split fp32 inputs into bf16 hi/lo
    split_kernel<<<BS_*D_/1024, 256>>>(Q, iQh, iQl, BS_*D_);
    split_kernel<<<BS_*D_/1024, 256>>>(K, iKh, iKl, BS_*D_);
    split_kernel<<<BS_*D_/1024, 256>>>(V, iVh, iVl, BS_*D_);
    split_kernel<<<D_*D_/1024, 256>>>(Wq, wqh, wql, D_*D_);
    split_kernel<<<D_*D_/1024, 256>>>(Wk, wkh, wkl, D_*D_);
    split_kernel<<<D_*D_/1024, 256>>>(Wv, wvh, wvl, D_*D_);
    split_kernel<<<D_*D_/1024, 256>>>(Wo, woh, wol, D_*D_);

    // 1) projections: q, k (split-bf16 out); v -> per-head transposed split-bf16
    {
        dim3 g(D_/128, BS_/128, 1);
        mma_gemm<128,0,1><<<g, 256, SM128>>>(iQh, iQl, wqh, wql,
            nullptr, qh, ql, D_, D_, D_, D_, 0,0,0,0,0,0, 1, 1.0f);
        mma_gemm<128,0,1><<<g, 256, SM128>>>(iKh, iKl, wkh, wkl,
            nullptr, kh, kl, D_, D_, D_, D_, 0,0,0,0,0,0, 1, 1.0f);
        mma_gemm<128,0,2><<<g, 256, SM128>>>(iVh, iVl, wvh, wvl,
            nullptr, vth, vtl, D_, D_, D_, D_, 0,0,0,0,0,0, 1, 1.0f);
    }

    // 2) scores = 0.125 * q @ k^T -> weights (fp32, pre-softmax)
    {
        dim3 g(S_/128, S_/128, B_*H_);
        mma_gemm<128,0,0><<<g, 256, SM128>>>(qh, ql, kh, kl,
            weights, nullptr, nullptr,
            HD_, D_, D_, S_,
            (long)S_*D_, (long)HD_, (long)S_*D_, (long)HD_,
            (long)H_*S_*S_, (long)S_*S_, H_, 0.125f);
    }

    // 3) softmax in place: one read + one write per element
    softmax_rows2048<<<B_*H_*S_, 256>>>(weights);

    // 4) cat = softmax(scores) @ v  (A fp32 split on load; B = v^T per head)
    {
        dim3 g(1, S_/128, B_*H_);
        mma_gemm<64,1,1><<<g, 256, SM64>>>(weights, nullptr, vth, vtl,
            nullptr, cath, catl,
            S_, S_, S_, D_,
            (long)H_*S_*S_, (long)S_*S_,
            (long)H_*HD_*S_, (long)HD_*S_,
            (long)S_*D_, (long)HD_, H_, 1.0f);
    }

    // 5) final = cat @ Wo^T (fp32 out)
    {
        dim3 g(D_/128, BS_/128, 1);
        mma_gemm<128,0,0><<<g, 256, SM128>>>(cath, catl, woh, wol,
            final_out, nullptr, nullptr,
            D_, D_, D_, D_, 0,0,0,0,0,0, 1, 1.0f);
    }
}